// round 2
// baseline (speedup 1.0000x reference)
#include <cuda_runtime.h>
#include <math.h>

#define F_N   65536
#define LPL   8
#define NLNK  8192
#define DGD   64
#define DD    32
#define NITER 8

// ---------------- device scratch (no allocations allowed) ----------------
__device__ float g_path[F_N * DD];            // 8 MB   path_state
__device__ float g_link[NLNK * DD];           // 1 MB   link_state
__device__ float g_mlx [NLNK * 96];           // 3 MB   link_state @ pg_w + b0
__device__ float g_pss [(size_t)F_N * 9 * DD];// 75.5MB [F,9,32]

// ---------------- math helpers ----------------
__device__ __forceinline__ float seluf(float x) {
    const float sc = 1.0507009873554804934f;
    const float al = 1.6732632423543772848f;
    return x > 0.f ? sc * x : sc * al * expm1f(x);
}
__device__ __forceinline__ float sigmoidf(float x) {
    return __fdividef(1.0f, 1.0f + __expf(-x));
}

// ---------------- flow embedding: path_state = MLP(pf) ----------------
__global__ __launch_bounds__(256) void k_flow_embed(
    const float* __restrict__ tr, const float* __restrict__ ln,
    const float* __restrict__ lp, const float* __restrict__ pd,
    const float* __restrict__ w1, const float* __restrict__ b1,
    const float* __restrict__ w2, const float* __restrict__ b2)
{
    int w = threadIdx.x >> 5, lane = threadIdx.x & 31;
    int f = blockIdx.x * 8 + w;
    __shared__ __align__(16) float buf[8][32];
    float p0 = (tr[f] - 0.5f) * 2.0f;
    float p1 = (ln[f] - 0.5f) * 2.0f;
    float p2 = (lp[f] - 0.1f) * 5.0f;
    float p3 = (pd[f] - 0.2f) * 3.0f;
    float t1 = b1[lane];
    t1 = fmaf(p0, w1[lane],      t1);
    t1 = fmaf(p1, w1[32 + lane], t1);
    t1 = fmaf(p2, w1[64 + lane], t1);
    t1 = fmaf(p3, w1[96 + lane], t1);
    t1 = seluf(t1);
    buf[w][lane] = t1;
    __syncwarp();
    float o = b2[lane];
    #pragma unroll
    for (int j = 0; j < 32; j++) o = fmaf(buf[w][j], w2[j*32 + lane], o);
    g_path[f*32 + lane] = seluf(o);
}

// ---------------- link embedding (fused per-link load computation) ----------------
__global__ __launch_bounds__(256) void k_link_embed(
    const float* __restrict__ tr, const float* __restrict__ cap,
    const int* __restrict__ ffl,
    const float* __restrict__ w1, const float* __restrict__ b1,
    const float* __restrict__ w2, const float* __restrict__ b2)
{
    int w = threadIdx.x >> 5, lane = threadIdx.x & 31;
    int l = blockIdx.x * 8 + w;
    __shared__ __align__(16) float buf[8][32];
    float s = tr[ffl[l*64 + lane]] + tr[ffl[l*64 + 32 + lane]];
    #pragma unroll
    for (int sh = 16; sh > 0; sh >>= 1) s += __shfl_xor_sync(0xffffffffu, s, sh);
    float c = cap[l];
    float load = (s * (1.0f/64.0f)) / c;
    float p0 = (c - 1.0f);          // (x-1.0)*1.0
    float t1 = b1[lane];
    t1 = fmaf(p0,   w1[lane],      t1);
    t1 = fmaf(load, w1[32 + lane], t1);
    t1 = seluf(t1);
    buf[w][lane] = t1;
    __syncwarp();
    float o = b2[lane];
    #pragma unroll
    for (int j = 0; j < 32; j++) o = fmaf(buf[w][j], w2[j*32 + lane], o);
    g_link[l*32 + lane] = seluf(o);
}

// ---------------- mlx = link_state @ pg_w + b0 (per iteration) ----------------
__global__ __launch_bounds__(256) void k_mlx(
    const float* __restrict__ pg_w, const float* __restrict__ pg_b)
{
    int w = threadIdx.x >> 5, lane = threadIdx.x & 31;
    int l = blockIdx.x * 8 + w;
    __shared__ __align__(16) float xbuf[8][32];
    float x = g_link[l*32 + lane];
    xbuf[w][lane] = x;
    __syncwarp();
    float az = pg_b[lane], ar = pg_b[32 + lane], ah = pg_b[64 + lane];
    #pragma unroll
    for (int j = 0; j < 32; j++) {
        float xj = xbuf[w][j];
        az = fmaf(xj, pg_w[j*96 + lane],      az);
        ar = fmaf(xj, pg_w[j*96 + 32 + lane], ar);
        ah = fmaf(xj, pg_w[j*96 + 64 + lane], ah);
    }
    g_mlx[l*96 + lane]      = az;
    g_mlx[l*96 + 32 + lane] = ar;
    g_mlx[l*96 + 64 + lane] = ah;
}

// ---------------- path GRU scan over LP=8 links; writes pss[F,9,32] ----------------
__global__ __launch_bounds__(256) void k_path(
    const float* __restrict__ pg_u, const float* __restrict__ pg_b,
    const int* __restrict__ l2f)
{
    int w = threadIdx.x >> 5, lane = threadIdx.x & 31;
    int f = blockIdx.x * 8 + w;
    __shared__ __align__(16) float hbuf[8][32];

    // recurrent weights for this lane's 3 gate outputs, held in registers
    float uz[32], ur[32], uh[32];
    #pragma unroll
    for (int j = 0; j < 32; j++) {
        uz[j] = pg_u[j*96 + lane];
        ur[j] = pg_u[j*96 + 32 + lane];
        uh[j] = pg_u[j*96 + 64 + lane];
    }
    float bz = pg_b[96 + lane], br = pg_b[96 + 32 + lane], bh = pg_b[96 + 64 + lane];

    float h = g_path[f*32 + lane];
    float* pss = g_pss + (size_t)f * 9 * 32;
    pss[lane] = h;
    hbuf[w][lane] = h;
    __syncwarp();

    #pragma unroll
    for (int t = 0; t < 8; t++) {
        int li = l2f[f*8 + t];
        const float* mrow = g_mlx + li * 96;
        float mz = mrow[lane], mr = mrow[32 + lane], mh = mrow[64 + lane];
        float az = bz, ar = br, ah = bh;
        #pragma unroll
        for (int j = 0; j < 32; j += 4) {
            float4 hv = *(const float4*)&hbuf[w][j];
            az = fmaf(hv.x, uz[j],   az); ar = fmaf(hv.x, ur[j],   ar); ah = fmaf(hv.x, uh[j],   ah);
            az = fmaf(hv.y, uz[j+1], az); ar = fmaf(hv.y, ur[j+1], ar); ah = fmaf(hv.y, uh[j+1], ah);
            az = fmaf(hv.z, uz[j+2], az); ar = fmaf(hv.z, ur[j+2], ar); ah = fmaf(hv.z, uh[j+2], ah);
            az = fmaf(hv.w, uz[j+3], az); ar = fmaf(hv.w, ur[j+3], ar); ah = fmaf(hv.w, uh[j+3], ah);
        }
        float z = sigmoidf(mz + az);
        float r = sigmoidf(mr + ar);
        float c = tanhf(mh + r * ah);
        h = fmaf(z, h, (1.f - z) * c);
        pss[(t+1)*32 + lane] = h;
        __syncwarp();
        hbuf[w][lane] = h;
        __syncwarp();
    }
    g_path[f*32 + lane] = h;
}

// ---------------- link update: attention aggregation + link GRU ----------------
__global__ __launch_bounds__(256) void k_link(
    const float* __restrict__ att_w, const float* __restrict__ att_b,
    const float* __restrict__ lg_w, const float* __restrict__ lg_u,
    const float* __restrict__ lg_b,
    const int* __restrict__ ffl, const int* __restrict__ fpos)
{
    int w = threadIdx.x >> 5, lane = threadIdx.x & 31;
    int l = blockIdx.x * 8 + w;
    __shared__ float sw[32*96];
    __shared__ float su[32*96];
    __shared__ __align__(16) float vbuf[8][32];
    __shared__ __align__(16) float xbuf[8][32];
    for (int i = threadIdx.x; i < 32*96; i += 256) { sw[i] = lg_w[i]; su[i] = lg_u[i]; }
    float aw[32];
    #pragma unroll
    for (int j = 0; j < 32; j++) aw[j] = att_w[j*32 + lane];
    float ab = att_b[lane];
    __syncthreads();

    float agg = 0.f;
    for (int d = 0; d < 64; d++) {
        int fidx = ffl[l*64 + d];
        int p    = fpos[l*64 + d];
        float v = g_pss[((size_t)fidx * 9 + p) * 32 + lane];
        vbuf[w][lane] = v;
        __syncwarp();
        float a = ab;
        #pragma unroll
        for (int j = 0; j < 32; j += 4) {
            float4 vv = *(const float4*)&vbuf[w][j];
            a = fmaf(vv.x, aw[j],   a);
            a = fmaf(vv.y, aw[j+1], a);
            a = fmaf(vv.z, aw[j+2], a);
            a = fmaf(vv.w, aw[j+3], a);
        }
        a = a > 0.f ? a : 0.2f * a;                    // leaky_relu(0.2)
        float m = a;                                    // softmax over D (lanes)
        #pragma unroll
        for (int s = 16; s > 0; s >>= 1) m = fmaxf(m, __shfl_xor_sync(0xffffffffu, m, s));
        float e = __expf(a - m);
        float ssum = e;
        #pragma unroll
        for (int s = 16; s > 0; s >>= 1) ssum += __shfl_xor_sync(0xffffffffu, ssum, s);
        agg = fmaf(__fdividef(e, ssum), v, agg);
        __syncwarp();
    }

    // link GRU: h = link_state[l], x = agg
    float h = g_link[l*32 + lane];
    xbuf[w][lane] = agg;
    vbuf[w][lane] = h;
    __syncwarp();
    float az = lg_b[lane], ar = lg_b[32 + lane], ah = lg_b[64 + lane];
    float hz = lg_b[96 + lane], hr = lg_b[96 + 32 + lane], hh = lg_b[96 + 64 + lane];
    #pragma unroll
    for (int j = 0; j < 32; j++) {
        float xj = xbuf[w][j], hj = vbuf[w][j];
        az = fmaf(xj, sw[j*96 + lane],      az);
        ar = fmaf(xj, sw[j*96 + 32 + lane], ar);
        ah = fmaf(xj, sw[j*96 + 64 + lane], ah);
        hz = fmaf(hj, su[j*96 + lane],      hz);
        hr = fmaf(hj, su[j*96 + 32 + lane], hr);
        hh = fmaf(hj, su[j*96 + 64 + lane], hh);
    }
    float z = sigmoidf(az + hz);
    float r = sigmoidf(ar + hr);
    float c = tanhf(ah + r * hh);
    g_link[l*32 + lane] = fmaf(z, h, (1.f - z) * c);
}

// ---------------- readout: one thread per (flow, path-slot), 8-lane reduce ----------------
__global__ __launch_bounds__(256) void k_readout(
    const float* __restrict__ w1, const float* __restrict__ b1,
    const float* __restrict__ w2, const float* __restrict__ b2,
    const float* __restrict__ w3, const float* __restrict__ b3,
    const int* __restrict__ l2f, const float* __restrict__ cap,
    const float* __restrict__ pd, float* __restrict__ out)
{
    __shared__ float sw1[32*16];
    __shared__ float sw2[16*8];
    __shared__ float sw3[8];
    __shared__ float sb1[16], sb2[8];
    if (threadIdx.x < 32*16) sw1[threadIdx.x] = w1[threadIdx.x];
    if (threadIdx.x < 16*8)  sw2[threadIdx.x] = w2[threadIdx.x];
    if (threadIdx.x < 8)     sw3[threadIdx.x] = w3[threadIdx.x];
    if (threadIdx.x < 16)    sb1[threadIdx.x] = b1[threadIdx.x];
    if (threadIdx.x < 8)     sb2[threadIdx.x] = b2[threadIdx.x];
    __syncthreads();

    int tid = blockIdx.x * 256 + threadIdx.x;
    int f = tid >> 3, t = tid & 7;

    float s[32];
    const float4* row = (const float4*)(g_pss + ((size_t)f * 9 + (t + 1)) * 32);
    #pragma unroll
    for (int i = 0; i < 8; i++) {
        float4 v = row[i];
        s[4*i] = v.x; s[4*i+1] = v.y; s[4*i+2] = v.z; s[4*i+3] = v.w;
    }
    float h1[16];
    #pragma unroll
    for (int k = 0; k < 16; k++) {
        float a = sb1[k];
        #pragma unroll
        for (int j = 0; j < 32; j++) a = fmaf(s[j], sw1[j*16 + k], a);
        h1[k] = seluf(a);
    }
    float h2[8];
    #pragma unroll
    for (int k = 0; k < 8; k++) {
        float a = sb2[k];
        #pragma unroll
        for (int j = 0; j < 16; j++) a = fmaf(h1[j], sw2[j*8 + k], a);
        h2[k] = seluf(a);
    }
    float o = b3[0];
    #pragma unroll
    for (int j = 0; j < 8; j++) o = fmaf(h2[j], sw3[j], o);
    float occ = fmaxf(o, 0.f) + log1pf(__expf(-fabsf(o)));   // softplus, stable
    float c = cap[l2f[f*8 + t]];
    float val = occ / c;
    val += __shfl_xor_sync(0xffffffffu, val, 1);
    val += __shfl_xor_sync(0xffffffffu, val, 2);
    val += __shfl_xor_sync(0xffffffffu, val, 4);
    if (t == 0) out[f] = val + pd[f];
}

// ---------------- launch ----------------
extern "C" void kernel_launch(void* const* d_in, const int* in_sizes, int n_in,
                              void* d_out, int out_size)
{
    const float* flow_traffic = (const float*)d_in[0];
    const float* flow_length  = (const float*)d_in[1];
    const float* flow_loss    = (const float*)d_in[2];
    const float* flow_pdelay  = (const float*)d_in[3];
    /* d_in[4] flow_packet_size unused */
    const float* link_cap     = (const float*)d_in[5];
    const int*   l2f          = (const int*)d_in[6];
    const int*   ffl          = (const int*)d_in[7];
    const int*   fpos         = (const int*)d_in[8];
    const float* fe_w1 = (const float*)d_in[9];
    const float* fe_b1 = (const float*)d_in[10];
    const float* fe_w2 = (const float*)d_in[11];
    const float* fe_b2 = (const float*)d_in[12];
    const float* le_w1 = (const float*)d_in[13];
    const float* le_b1 = (const float*)d_in[14];
    const float* le_w2 = (const float*)d_in[15];
    const float* le_b2 = (const float*)d_in[16];
    const float* att_w = (const float*)d_in[17];
    const float* att_b = (const float*)d_in[18];
    const float* pg_w  = (const float*)d_in[19];
    const float* pg_u  = (const float*)d_in[20];
    const float* pg_b  = (const float*)d_in[21];
    const float* lg_w  = (const float*)d_in[22];
    const float* lg_u  = (const float*)d_in[23];
    const float* lg_b  = (const float*)d_in[24];
    const float* ro_w1 = (const float*)d_in[25];
    const float* ro_b1 = (const float*)d_in[26];
    const float* ro_w2 = (const float*)d_in[27];
    const float* ro_b2 = (const float*)d_in[28];
    const float* ro_w3 = (const float*)d_in[29];
    const float* ro_b3 = (const float*)d_in[30];
    float* out = (float*)d_out;

    k_flow_embed<<<F_N/8, 256>>>(flow_traffic, flow_length, flow_loss, flow_pdelay,
                                 fe_w1, fe_b1, fe_w2, fe_b2);
    k_link_embed<<<NLNK/8, 256>>>(flow_traffic, link_cap, ffl,
                                  le_w1, le_b1, le_w2, le_b2);
    for (int it = 0; it < NITER; it++) {
        k_mlx <<<NLNK/8, 256>>>(pg_w, pg_b);
        k_path<<<F_N/8, 256>>>(pg_u, pg_b, l2f);
        k_link<<<NLNK/8, 256>>>(att_w, att_b, lg_w, lg_u, lg_b, ffl, fpos);
    }
    k_readout<<<(F_N*LPL)/256, 256>>>(ro_w1, ro_b1, ro_w2, ro_b2, ro_w3, ro_b3,
                                      l2f, link_cap, flow_pdelay, out);
}